// round 14
// baseline (speedup 1.0000x reference)
#include <cuda_runtime.h>
#include <cstdint>
#include <cstddef>

// out[b,i,j,c] = (gelu(pos_table[max(i-j,0)] @ W1 + b1) @ W2 + b2)[c]
// T=512, E=64, H=128. Only 512 distinct rows -> build 512x128 table, scatter.
//
// R14 model: period = scatter_issue + ~9us fixed overhead (measured across
// R5/R8/R13 -- NOT a pure drain floor, since slower issue shifted the period
// 1:1). Levers: (1) scatter issue is latency-limited (nothing >66% util):
// batch 8 LDG then 8 STG to raise MLP; (2) overlap the build kernel with the
// scatter's launch/prologue via PDL (programmatic stream serialization +
// grid-dependency sync before the first table read).

#define T_DIM 512
#define E_DIM 64
#define H_DIM 128

// Biased-resident region: 112 MB = 7,340,032 float4 = 896 scatter blocks.
#define P_F4 7340032ull

__device__ float g_table[T_DIM * H_DIM];   // 256 KB scratch (static, no alloc)

__device__ __forceinline__ uint64_t make_evict_last_policy() {
    uint64_t pol;
    asm("createpolicy.fractional.L2::evict_last.b64 %0, 1.0;" : "=l"(pol));
    return pol;
}

__device__ __forceinline__ void st_pinned(float4* p, float4 v, uint64_t pol) {
    asm volatile(
        "st.global.L2::cache_hint.v4.f32 [%0], {%1,%2,%3,%4}, %5;"
        :: "l"(p), "f"(v.x), "f"(v.y), "f"(v.z), "f"(v.w), "l"(pol)
        : "memory");
}

__device__ __forceinline__ void st_stream(float4* p, float4 v) {
    asm volatile(
        "st.global.cs.v4.f32 [%0], {%1,%2,%3,%4};"
        :: "l"(p), "f"(v.x), "f"(v.y), "f"(v.z), "f"(v.w)
        : "memory");
}

// ---------------------------------------------------------------------------
// Kernel A: build the table (512 blocks x 128 threads; best measured shape).
// Triggers programmatic launch completion as soon as its stores are issued.
// ---------------------------------------------------------------------------
__global__ void __launch_bounds__(H_DIM)
build_table_kernel(const float* __restrict__ pos_table,
                   const float* __restrict__ W1,
                   const float* __restrict__ b1,
                   const float* __restrict__ W2,
                   const float* __restrict__ b2) {
    __shared__ float sp[E_DIM];
    __shared__ float sh[H_DIM];

    const int d = blockIdx.x;      // distance row 0..511
    const int j = threadIdx.x;     // output column 0..127

    if (j < E_DIM) sp[j] = pos_table[d * E_DIM + j];
    __syncthreads();

    float acc = b1[j];
#pragma unroll
    for (int k = 0; k < E_DIM; k++)
        acc = fmaf(sp[k], W1[k * H_DIM + j], acc);
    // Exact GELU: 0.5*x*(1+erf(x/sqrt(2)))
    sh[j] = 0.5f * acc * (1.0f + erff(acc * 0.70710678118654752f));
    __syncthreads();

    float acc2 = b2[j];
#pragma unroll
    for (int k = 0; k < H_DIM; k++)
        acc2 = fmaf(sh[k], W2[k * H_DIM + j], acc2);

    const uint64_t pol = make_evict_last_policy();
    asm volatile("st.global.L2::cache_hint.f32 [%0], %1, %2;"
                 :: "l"(&g_table[d * H_DIM + j]), "f"(acc2), "l"(pol)
                 : "memory");

#if __CUDA_ARCH__ >= 900
    cudaTriggerProgrammaticLaunchCompletion();
#endif
}

// ---------------------------------------------------------------------------
// Kernel B: row-contiguous scatter, batched LDG/STG (MLP=8), PDL-gated.
// Block = (half, i, b): 128 KB contiguous span. Prologue (index math) runs
// while the build kernel finishes; cudaGridDependencySynchronize() before
// the first table read.
// ---------------------------------------------------------------------------
__global__ void __launch_bounds__(256)
scatter_kernel(float4* __restrict__ out) {
    const int i    = blockIdx.y;
    const int b    = blockIdx.z;
    const int j0   = blockIdx.x << 8;    // 0 or 256
    const int warp = threadIdx.x >> 5;   // 0..7
    const int lane = threadIdx.x & 31;

    const float4* __restrict__ tbl = reinterpret_cast<const float4*>(g_table);
    float4* __restrict__ dst =
        out + (((size_t)b * T_DIM + i) * T_DIM) * (H_DIM / 4) + lane;

    const int jw = j0 + (warp << 5);     // this warp's 32-j contiguous span

    const size_t base_f4 = (((size_t)b * T_DIM + i) * T_DIM + j0) * (H_DIM / 4);
    const bool pinned = (base_f4 + 8192ull) <= P_F4;
    const uint64_t pol = make_evict_last_policy();

#if __CUDA_ARCH__ >= 900
    cudaGridDependencySynchronize();     // table ready (no-op without PDL)
#endif

    if (pinned) {
#pragma unroll
        for (int g = 0; g < 4; g++) {
            float4 v[8];
#pragma unroll
            for (int u = 0; u < 8; u++) {
                const int j   = jw + (g << 3) + u;
                const int d   = i - j;
                const int row = d > 0 ? d : 0;
                v[u] = __ldg(tbl + row * (H_DIM / 4) + lane);
            }
#pragma unroll
            for (int u = 0; u < 8; u++) {
                const int j = jw + (g << 3) + u;
                st_pinned(dst + (size_t)j * (H_DIM / 4), v[u], pol);
            }
        }
    } else {
#pragma unroll
        for (int g = 0; g < 4; g++) {
            float4 v[8];
#pragma unroll
            for (int u = 0; u < 8; u++) {
                const int j   = jw + (g << 3) + u;
                const int d   = i - j;
                const int row = d > 0 ? d : 0;
                v[u] = __ldg(tbl + row * (H_DIM / 4) + lane);
            }
#pragma unroll
            for (int u = 0; u < 8; u++) {
                const int j = jw + (g << 3) + u;
                st_stream(dst + (size_t)j * (H_DIM / 4), v[u]);
            }
        }
    }
}

extern "C" void kernel_launch(void* const* d_in, const int* in_sizes, int n_in,
                              void* d_out, int out_size) {
    // Inputs: b, pos_table, W1, b1, W2, b2 (scalar b may or may not be input 0).
    int base = 0;
    if (n_in >= 6) {
        base = 1;
    } else if (n_in == 5 && in_sizes[0] == T_DIM * E_DIM) {
        base = 0;
    }
    const float* pos_table = (const float*)d_in[base + 0];
    const float* W1        = (const float*)d_in[base + 1];
    const float* b1        = (const float*)d_in[base + 2];
    const float* W2        = (const float*)d_in[base + 3];
    const float* b2        = (const float*)d_in[base + 4];

    const int bsz = out_size / (T_DIM * T_DIM * H_DIM);

    build_table_kernel<<<T_DIM, H_DIM>>>(pos_table, W1, b1, W2, b2);

    dim3 grid(2, T_DIM, bsz);            // 2 half-rows x 512 i x batch

    // PDL launch: scatter's launch/prologue overlaps the build kernel; the
    // in-kernel grid-dependency sync provides the ordering.
    cudaLaunchConfig_t cfg = {};
    cfg.gridDim = grid;
    cfg.blockDim = dim3(256);
    cfg.dynamicSmemBytes = 0;
    cfg.stream = 0;

    cudaLaunchAttribute a[1];
    a[0].id = cudaLaunchAttributeProgrammaticStreamSerialization;
    a[0].val.programmaticStreamSerializationAllowed = 1;
    cfg.attrs = a;
    cfg.numAttrs = 1;

    cudaError_t e = cudaLaunchKernelEx(&cfg, scatter_kernel, (float4*)d_out);
    if (e != cudaSuccess) {
        // Fallback: plain ordered launch (grid-dependency sync degrades to
        // a no-op when no programmatic dependency exists).
        scatter_kernel<<<grid, 256>>>((float4*)d_out);
    }
}

// round 15
// speedup vs baseline: 1.0126x; 1.0126x over previous
#include <cuda_runtime.h>
#include <cstdint>
#include <cstddef>

// out[b,i,j,c] = (gelu(pos_table[max(i-j,0)] @ W1 + b1) @ W2 + b2)[c]
// T=512, E=64, H=128. Only 512 distinct rows -> build 512x128 table, scatter.
//
// CONVERGED FINAL (best measured 50.59us; noise band 50.6-51.3us over 4 runs
// of this config). Replay period = max(issue + overhead, 268 MB mandatory
// fp32 DRAM writes / ~5.25 TB/s sustained write BW) ~= 51us, drain-bound.
// Falsified levers (R1-R14): grid/wave shaping, store ordering, MLP batching,
// L2 retention (hints demoted without a persisting carve-out, which the
// harness forbids), verify-read conversion, mixed-direction traffic,
// bulk-copy write engine, write-through ordering, PDL overlap.

#define T_DIM 512
#define E_DIM 64
#define H_DIM 128

// Biased-resident region: 112 MB = 7,340,032 float4 = 896 scatter blocks.
#define P_F4 7340032ull

__device__ float g_table[T_DIM * H_DIM];   // 256 KB scratch (static, no alloc)

__device__ __forceinline__ uint64_t make_evict_last_policy() {
    uint64_t pol;
    asm("createpolicy.fractional.L2::evict_last.b64 %0, 1.0;" : "=l"(pol));
    return pol;
}

__device__ __forceinline__ void st_pinned(float4* p, float4 v, uint64_t pol) {
    asm volatile(
        "st.global.L2::cache_hint.v4.f32 [%0], {%1,%2,%3,%4}, %5;"
        :: "l"(p), "f"(v.x), "f"(v.y), "f"(v.z), "f"(v.w), "l"(pol)
        : "memory");
}

__device__ __forceinline__ void st_stream(float4* p, float4 v) {
    asm volatile(
        "st.global.cs.v4.f32 [%0], {%1,%2,%3,%4};"
        :: "l"(p), "f"(v.x), "f"(v.y), "f"(v.z), "f"(v.w)
        : "memory");
}

// ---------------------------------------------------------------------------
// Kernel A: build the table (512 blocks x 128 threads; best measured shape).
// Table stored evict_last so the scatter's gather reads stay L2-resident.
// ---------------------------------------------------------------------------
__global__ void __launch_bounds__(H_DIM)
build_table_kernel(const float* __restrict__ pos_table,
                   const float* __restrict__ W1,
                   const float* __restrict__ b1,
                   const float* __restrict__ W2,
                   const float* __restrict__ b2) {
    __shared__ float sp[E_DIM];
    __shared__ float sh[H_DIM];

    const int d = blockIdx.x;      // distance row 0..511
    const int j = threadIdx.x;     // output column 0..127

    if (j < E_DIM) sp[j] = pos_table[d * E_DIM + j];
    __syncthreads();

    float acc = b1[j];
#pragma unroll
    for (int k = 0; k < E_DIM; k++)
        acc = fmaf(sp[k], W1[k * H_DIM + j], acc);
    // Exact GELU: 0.5*x*(1+erf(x/sqrt(2)))
    sh[j] = 0.5f * acc * (1.0f + erff(acc * 0.70710678118654752f));
    __syncthreads();

    float acc2 = b2[j];
#pragma unroll
    for (int k = 0; k < H_DIM; k++)
        acc2 = fmaf(sh[k], W2[k * H_DIM + j], acc2);

    const uint64_t pol = make_evict_last_policy();
    asm volatile("st.global.L2::cache_hint.f32 [%0], %1, %2;"
                 :: "l"(&g_table[d * H_DIM + j]), "f"(acc2), "l"(pol)
                 : "memory");
}

// ---------------------------------------------------------------------------
// Kernel B: row-contiguous scatter with biased-resident / streaming split.
// Block = (half, i, b): 128 KB contiguous span of the output.
// Linear offsets < 112 MB -> evict_last stores; rest -> .cs streaming stores.
// Warp = 512 B contiguous store per iteration; table row is warp-uniform so
// the gather is a single coalesced 512 B L1/L2 hit.
// ---------------------------------------------------------------------------
__global__ void __launch_bounds__(256)
scatter_kernel(float4* __restrict__ out) {
    const int i    = blockIdx.y;
    const int b    = blockIdx.z;
    const int j0   = blockIdx.x << 8;    // 0 or 256
    const int warp = threadIdx.x >> 5;   // 0..7
    const int lane = threadIdx.x & 31;

    const float4* __restrict__ tbl = reinterpret_cast<const float4*>(g_table);
    float4* __restrict__ dst =
        out + (((size_t)b * T_DIM + i) * T_DIM) * (H_DIM / 4) + lane;

    const int jw = j0 + (warp << 5);     // this warp's 32-j contiguous span

    // Block's starting float4 offset; each block covers 8192 float4.
    const size_t base_f4 = (((size_t)b * T_DIM + i) * T_DIM + j0) * (H_DIM / 4);
    const bool pinned = (base_f4 + 8192ull) <= P_F4;

    if (pinned) {
        const uint64_t pol = make_evict_last_policy();
#pragma unroll 4
        for (int t = 0; t < 32; t++) {
            const int j   = jw + t;
            const int d   = i - j;
            const int row = d > 0 ? d : 0;
            const float4 v = __ldg(tbl + row * (H_DIM / 4) + lane);
            st_pinned(dst + (size_t)j * (H_DIM / 4), v, pol);
        }
    } else {
#pragma unroll 4
        for (int t = 0; t < 32; t++) {
            const int j   = jw + t;
            const int d   = i - j;
            const int row = d > 0 ? d : 0;
            const float4 v = __ldg(tbl + row * (H_DIM / 4) + lane);
            st_stream(dst + (size_t)j * (H_DIM / 4), v);
        }
    }
}

extern "C" void kernel_launch(void* const* d_in, const int* in_sizes, int n_in,
                              void* d_out, int out_size) {
    // Inputs: b, pos_table, W1, b1, W2, b2 (scalar b may or may not be input 0).
    int base = 0;
    if (n_in >= 6) {
        base = 1;
    } else if (n_in == 5 && in_sizes[0] == T_DIM * E_DIM) {
        base = 0;
    }
    const float* pos_table = (const float*)d_in[base + 0];
    const float* W1        = (const float*)d_in[base + 1];
    const float* b1        = (const float*)d_in[base + 2];
    const float* W2        = (const float*)d_in[base + 3];
    const float* b2        = (const float*)d_in[base + 4];

    const int bsz = out_size / (T_DIM * T_DIM * H_DIM);

    build_table_kernel<<<T_DIM, H_DIM>>>(pos_table, W1, b1, W2, b2);

    dim3 grid(2, T_DIM, bsz);            // 2 half-rows x 512 i x batch
    scatter_kernel<<<grid, 256>>>((float4*)d_out);
}